// round 1
// baseline (speedup 1.0000x reference)
#include <cuda_runtime.h>
#include <cstdint>

// Problem constants (fixed by the reference)
#define BATCH   64
#define LSEQ    16384
#define FCH     128
#define KW      16
#define OUT_LEN 16369            // (16384 - 16) + 1
#define TILE_O  64               // output positions per block
#define NTHREADS 256             // 8 warps
#define O_PER_WARP 8             // 64 / 8 warps

// ---------------- packed f32x2 helpers (Blackwell) ----------------
__device__ __forceinline__ unsigned long long pack2(float lo, float hi) {
    unsigned long long r;
    asm("mov.b64 %0, {%1, %2};" : "=l"(r) : "f"(lo), "f"(hi));
    return r;
}
__device__ __forceinline__ void ffma2(unsigned long long& d,
                                      unsigned long long a,
                                      unsigned long long b,
                                      unsigned long long c) {
    asm("fma.rn.f32x2 %0, %1, %2, %3;" : "=l"(d) : "l"(a), "l"(b), "l"(c));
}
__device__ __forceinline__ void unpack2(unsigned long long v, float& lo, float& hi) {
    asm("mov.b64 {%0, %1}, %2;" : "=f"(lo), "=f"(hi) : "l"(v));
}

__global__ __launch_bounds__(NTHREADS, 2)
void speccnn1d_kernel(const float* __restrict__ x,
                      const float* __restrict__ kern,
                      float* __restrict__ out) {
    // Shared: weights transposed [k][f] for conflict-light packed reads,
    // plus x window pre-duplicated as {v,v} u64 for direct LDS.64 operands.
    __shared__ float ws[KW * FCH];                       // 8 KB
    __shared__ unsigned long long xs2[TILE_O + KW];      // 80 * 8B = 640 B

    const int tid  = threadIdx.x;
    const int b    = blockIdx.y;
    const int o0   = blockIdx.x * TILE_O;

    // ---- stage weights transposed: ws[k*F + f] = kern[f*K + k] ----
    #pragma unroll
    for (int i = 0; i < (KW * FCH) / NTHREADS; i++) {
        int idx = tid * ((KW * FCH) / NTHREADS) + i;     // 0..2047
        int f = idx >> 4;
        int k = idx & 15;
        ws[k * FCH + f] = kern[idx];
    }

    // ---- stage x window duplicated: xs2[i] = {x[o0+i], x[o0+i]} ----
    {
        const float* xb = x + (size_t)b * LSEQ;
        int i = tid;
        if (i < TILE_O + KW - 1) {                       // 79 elements
            int xi = o0 + i;
            float v = (xi < LSEQ) ? xb[xi] : 0.0f;
            xs2[i] = pack2(v, v);
        }
    }
    __syncthreads();

    const int lane = tid & 31;
    const int warp = tid >> 5;
    const int f0   = lane * 4;                           // this thread's 4 channels

    // ---- hoist weights into registers as packed pairs ----
    unsigned long long w0[KW], w1[KW];
    #pragma unroll
    for (int k = 0; k < KW; k++) {
        float2 a = *reinterpret_cast<const float2*>(&ws[k * FCH + f0]);
        float2 c = *reinterpret_cast<const float2*>(&ws[k * FCH + f0 + 2]);
        w0[k] = pack2(a.x, a.y);
        w1[k] = pack2(c.x, c.y);
    }

    float* outb = out + (size_t)b * OUT_LEN * FCH;

    // ---- each warp computes 8 consecutive o, 2 at a time ----
    #pragma unroll
    for (int j = 0; j < O_PER_WARP; j += 2) {
        const int lo = warp * O_PER_WARP + j;            // local o within tile
        const int o  = o0 + lo;

        unsigned long long a0 = 0ull, a1 = 0ull;         // accumulators for o
        unsigned long long b0 = 0ull, b1 = 0ull;         // accumulators for o+1

        #pragma unroll
        for (int k = 0; k < KW; k++) {
            unsigned long long xv0 = xs2[lo + k];        // broadcast LDS.64
            ffma2(a0, xv0, w0[k], a0);
            ffma2(a1, xv0, w1[k], a1);
            unsigned long long xv1 = xs2[lo + k + 1];    // CSE'd with next iter
            ffma2(b0, xv1, w0[k], b0);
            ffma2(b1, xv1, w1[k], b1);
        }

        if (o < OUT_LEN) {
            float v0, v1, v2, v3;
            unpack2(a0, v0, v1);
            unpack2(a1, v2, v3);
            float4 r;
            r.x = fmaxf(v0, 0.0f); r.y = fmaxf(v1, 0.0f);
            r.z = fmaxf(v2, 0.0f); r.w = fmaxf(v3, 0.0f);
            *reinterpret_cast<float4*>(&outb[(size_t)o * FCH + f0]) = r;
        }
        if (o + 1 < OUT_LEN) {
            float v0, v1, v2, v3;
            unpack2(b0, v0, v1);
            unpack2(b1, v2, v3);
            float4 r;
            r.x = fmaxf(v0, 0.0f); r.y = fmaxf(v1, 0.0f);
            r.z = fmaxf(v2, 0.0f); r.w = fmaxf(v3, 0.0f);
            *reinterpret_cast<float4*>(&outb[(size_t)(o + 1) * FCH + f0]) = r;
        }
    }
}

extern "C" void kernel_launch(void* const* d_in, const int* in_sizes, int n_in,
                              void* d_out, int out_size) {
    const float* x    = (const float*)d_in[0];   // (64, 16384) fp32
    const float* kern = (const float*)d_in[1];   // (128, 16)  fp32
    float* out        = (float*)d_out;           // (64, 16369, 128) fp32

    dim3 grid((OUT_LEN + TILE_O - 1) / TILE_O, BATCH);   // (256, 64)
    speccnn1d_kernel<<<grid, NTHREADS>>>(x, kern, out);
}